// round 4
// baseline (speedup 1.0000x reference)
#include <cuda_runtime.h>
#include <math.h>

#define BS    512
#define LNUM  68
#define IMG   224
#define RS    7
#define R2    49
#define LL    (LNUM * LNUM)     // 4624
#define NLM   (BS * LNUM)       // 34816
#define FULLM 0xFFFFFFFFu
#define MB    0x1FFFFu          // lanes 0..16 hold slots 32..48

#define K1_THREADS 256          // 8 warps -> 8 landmarks per block
#define K2_THREADS 256

__device__ float    g_median[NLM];
__device__ double   g_sumL = 0.0;
__device__ double   g_sumM = 0.0;
__device__ unsigned g_done = 0u;

// Sample one region slot s (0..48); exact replica of the reference's
// grid_sample-nearest arithmetic (rintf == jnp.round, half-even).
__device__ __forceinline__ float region_val(const float* __restrict__ dimg,
                                            float fx, float fy, int s)
{
    int p = s / RS, q = s - p * RS;
    float xp = (p == RS - 1) ? 3.5f : (-3.5f + (float)p * (7.0f / 6.0f));
    float xq = (q == RS - 1) ? 3.5f : (-3.5f + (float)q * (7.0f / 6.0f));
    xp = xp / 224.0f * 2.0f;
    xq = xq / 224.0f * 2.0f;
    float gy = fy + xp;                       // offsets[p][q] = (x[q], x[p])
    float gx = fx + xq;
    float iy = ((gy + 1.0f) * 224.0f - 1.0f) * 0.5f;
    float ix = ((gx + 1.0f) * 224.0f - 1.0f) * 0.5f;
    int yi = (int)rintf(iy);
    int xi = (int)rintf(ix);
    bool v = (yi >= 0) & (yi < IMG) & (xi >= 0) & (xi < IMG);
    int yc = min(max(yi, 0), IMG - 1);
    int xc = min(max(xi, 0), IMG - 1);
    float val = __ldg(dimg + yc * IMG + xc);
    return v ? val : 0.0f;
}

// ---- K1: region median per landmark, one warp per landmark ---------------
// Rank-by-broadcast: every lane counts, for its value(s), how many of the 49
// region values are < it (cl) and <= it (ce). The sought order statistic mi
// lies in exactly the value-interval(s) [cl, ce) that contain mi; all lanes
// matching hold the same value. Branch-free, no serial dependency chain.
__global__ __launch_bounds__(K1_THREADS) void k1_region_median(
    const float* __restrict__ depth,
    const float* __restrict__ lm,
    const float* __restrict__ sf,
    const float* __restrict__ bbox)
{
    int wid  = threadIdx.x >> 5;
    int lane = threadIdx.x & 31;
    int idx  = blockIdx.x * (K1_THREADS / 32) + wid;
    if (idx >= NLM) return;
    int b = idx / LNUM;

    float sf0 = __ldg(sf + b * 2 + 0), sf1 = __ldg(sf + b * 2 + 1);
    float bx  = __ldg(bbox + b * 4 + 0), by = __ldg(bbox + b * 4 + 1);
    float lmx = __ldg(lm + (size_t)idx * 2 + 0);
    float lmy = __ldg(lm + (size_t)idx * 2 + 1);
    float fx = (lmx - bx) * sf0 / 224.0f * 2.0f - 1.0f;
    float fy = (lmy - by) * sf1 / 224.0f * 2.0f - 1.0f;

    const float* dimg = depth + (size_t)b * IMG * IMG;
    const float  INF  = __int_as_float(0x7f800000);

    float v0 = region_val(dimg, fx, fy, lane);
    float v1 = (lane < 17) ? region_val(dimg, fx, fy, lane + 32) : INF;

    // target rank mi = (clamp(count(v<=THR),1,48)+48)/2
    unsigned le0 = __ballot_sync(FULLM, v0 <= 1e-4f);
    unsigned le1 = __ballot_sync(FULLM, v1 <= 1e-4f) & MB;
    int k  = __popc(le0) + __popc(le1);
    int st = min(max(k, 1), R2 - 1);
    int mi = (st + R2 - 1) >> 1;

    int cl0 = 0, ce0 = 0, cl1 = 0, ce1 = 0;
#pragma unroll
    for (int s = 0; s < R2; s++) {
        float w = (s < 32) ? __shfl_sync(FULLM, v0, s)
                           : __shfl_sync(FULLM, v1, s - 32);
        cl0 += (w <  v0); ce0 += (w <= v0);
        cl1 += (w <  v1); ce1 += (w <= v1);
    }

    bool c0 = (cl0 <= mi) & (mi < ce0);
    bool c1 = (lane < 17) & (cl1 <= mi) & (mi < ce1);
    unsigned b0 = __ballot_sync(FULLM, c0);
    unsigned b1 = __ballot_sync(FULLM, c1);
    float res;
    if (b0) res = __shfl_sync(FULLM, v0, __ffs(b0) - 1);
    else    res = __shfl_sync(FULLM, v1, __ffs(b1) - 1);
    if (lane == 0) g_median[idx] = res;
}

// ---- K2: per-batch median-of-medians + mask + pairwise loss --------------
__global__ __launch_bounds__(K2_THREADS) void k2_pairwise(
    const float* __restrict__ rel,
    float* __restrict__ out)
{
    __shared__ float  smed[LNUM];
    __shared__ float  smask[LNUM];
    __shared__ float  s_mom;
    __shared__ double redL[K2_THREADS / 32], redM[K2_THREADS / 32];
    __shared__ bool   s_last;

    int b    = blockIdx.x;
    int tid  = threadIdx.x;
    int wid  = tid >> 5;
    int lane = tid & 31;

    if (tid < LNUM) smed[tid] = g_median[b * LNUM + tid];
    __syncthreads();

    // lower median-of-medians (rank 33) via stable rank count
    float vraw = 0.0f;
    if (tid < LNUM) {
        vraw = smed[tid];
        int r = 0;
#pragma unroll 4
        for (int j = 0; j < LNUM; j++) {
            float w = smed[j];
            r += (w < vraw || (w == vraw && j < tid)) ? 1 : 0;
        }
        if (r == (LNUM - 1) / 2) s_mom = vraw;
    }
    __syncthreads();
    if (tid < LNUM) {
        smask[tid] = (fabsf(vraw - s_mom) < (90.0f / 500.0f)) ? 1.0f : 0.0f;
        smed[tid]  = vraw * 500.0f;
    }
    __syncthreads();

    // pairwise diff / mask / smooth-L1. Output: out[0]=loss, outd=out+1,
    // outm=out+1+BS*LL. outd[base+e] has global index 1+base+e; base%4==0,
    // so e≡3 (mod 4) gives 16B-aligned float4 stores.
    float* outd = out + 1;
    float* outm = out + 1 + (size_t)BS * LL;
    const size_t base = (size_t)b * LL;
    const float* relb = rel + base;
    float accL = 0.0f, accM = 0.0f;

    if (tid < 4) {                      // head e=0,1,2 and tail e=4623
        int e = (tid < 3) ? tid : (LL - 1);
        int i = e / LNUM;
        int j = e - i * LNUM;
        float diff = smed[i] - smed[j];
        float mk   = smask[i] * smask[j];
        float d    = relb[e] - diff;
        float ad   = fabsf(d);
        float c    = fminf(ad, 1.0f);
        float le   = c * (ad - 0.5f * c);
        outd[base + e] = diff;
        outm[base + e] = mk;
        accL += le * mk;
        accM += mk;
    }

    const int NGRP = (LL - 4) / 4;      // 1155 float4 groups, e = 3 + 4g
    for (int g = tid; g < NGRP; g += K2_THREADS) {
        int e0 = 3 + (g << 2);
        int i0 = e0 / LNUM;
        int j0 = e0 - i0 * LNUM;
        float dvv[4], mvv[4];
        float4 rv = *reinterpret_cast<const float4*>(relb + e0 - 3) ;  // dummy to avoid misuse
        (void)rv;
#pragma unroll
        for (int n = 0; n < 4; n++) {
            int jn = j0 + n;
            int wrap = (jn >= LNUM) ? 1 : 0;
            int in = i0 + wrap;
            jn -= LNUM * wrap;
            float diff = smed[in] - smed[jn];
            float mk   = smask[in] * smask[jn];
            float d    = relb[e0 + n] - diff;
            float ad   = fabsf(d);
            float c    = fminf(ad, 1.0f);
            float le   = c * (ad - 0.5f * c);
            dvv[n] = diff;
            mvv[n] = mk;
            accL += le * mk;
            accM += mk;
        }
        *reinterpret_cast<float4*>(outd + base + e0) =
            make_float4(dvv[0], dvv[1], dvv[2], dvv[3]);
        *reinterpret_cast<float4*>(outm + base + e0) =
            make_float4(mvv[0], mvv[1], mvv[2], mvv[3]);
    }

    // block reduce (double) + global atomics + last-block finalize
    double dL = (double)accL, dM = (double)accM;
#pragma unroll
    for (int o = 16; o > 0; o >>= 1) {
        dL += __shfl_down_sync(FULLM, dL, o);
        dM += __shfl_down_sync(FULLM, dM, o);
    }
    if (lane == 0) { redL[wid] = dL; redM[wid] = dM; }
    __syncthreads();
    if (tid == 0) {
        double tL = 0.0, tM = 0.0;
#pragma unroll
        for (int w = 0; w < K2_THREADS / 32; w++) { tL += redL[w]; tM += redM[w]; }
        atomicAdd(&g_sumL, tL);
        atomicAdd(&g_sumM, tM);
        __threadfence();
        unsigned n = atomicAdd(&g_done, 1u);
        s_last = (n == BS - 1);
    }
    __syncthreads();

    if (s_last && tid == 0) {
        __threadfence();
        double L = g_sumL, M = g_sumM;
        out[0] = (float)(L / (M + 1e-4));
        g_sumL = 0.0; g_sumM = 0.0; g_done = 0u;
    }
}

extern "C" void kernel_launch(void* const* d_in, const int* in_sizes, int n_in,
                              void* d_out, int out_size)
{
    const float* rel   = (const float*)d_in[0];   // [BS, L, L]
    const float* depth = (const float*)d_in[1];   // [BS, 1, IMG, IMG]
    const float* lm    = (const float*)d_in[2];   // [BS, L, 2]
    const float* sf    = (const float*)d_in[3];   // [BS, 2]
    const float* bbox  = (const float*)d_in[4];   // [BS, 4]
    float* out = (float*)d_out;                   // [loss | diff | mask]

    const int k1_blocks = (NLM + (K1_THREADS / 32) - 1) / (K1_THREADS / 32);
    k1_region_median<<<k1_blocks, K1_THREADS>>>(depth, lm, sf, bbox);
    k2_pairwise<<<BS, K2_THREADS>>>(rel, out);
}

// round 5
// speedup vs baseline: 1.0499x; 1.0499x over previous
#include <cuda_runtime.h>
#include <math.h>

#define BS    512
#define LNUM  68
#define IMG   224
#define RS    7
#define R2    49
#define LL    (LNUM * LNUM)     // 4624
#define NLM   (BS * LNUM)       // 34816
#define FULLM 0xFFFFFFFFu
#define MB    0x1FFFFu          // lanes 0..16 hold slots 32..48

#define K1_THREADS 256          // 8 warps -> 8 landmarks per block
#define K2_THREADS 256
#define SLICES    4             // K2 blocks per batch
#define NGRP      ((LL - 4) / 4)        // 1155 float4 groups per batch
#define GRP_PER_SLICE ((NGRP + SLICES - 1) / SLICES)   // 289

__device__ float    g_median[NLM];
__device__ double   g_sumL = 0.0;
__device__ double   g_sumM = 0.0;
__device__ unsigned g_done = 0u;

// Sample one region slot s (0..48); exact replica of the reference's
// grid_sample-nearest arithmetic (rintf == jnp.round, half-even).
__device__ __forceinline__ float region_val(const float* __restrict__ dimg,
                                            float fx, float fy, int s)
{
    int p = s / RS, q = s - p * RS;
    float xp = (p == RS - 1) ? 3.5f : (-3.5f + (float)p * (7.0f / 6.0f));
    float xq = (q == RS - 1) ? 3.5f : (-3.5f + (float)q * (7.0f / 6.0f));
    xp = xp / 224.0f * 2.0f;
    xq = xq / 224.0f * 2.0f;
    float gy = fy + xp;                       // offsets[p][q] = (x[q], x[p])
    float gx = fx + xq;
    float iy = ((gy + 1.0f) * 224.0f - 1.0f) * 0.5f;
    float ix = ((gx + 1.0f) * 224.0f - 1.0f) * 0.5f;
    int yi = (int)rintf(iy);
    int xi = (int)rintf(ix);
    bool v = (yi >= 0) & (yi < IMG) & (xi >= 0) & (xi < IMG);
    int yc = min(max(yi, 0), IMG - 1);
    int xc = min(max(xi, 0), IMG - 1);
    float val = __ldg(dimg + yc * IMG + xc);
    return v ? val : 0.0f;
}

// ---- K1: region median per landmark, one warp per landmark, quickselect ----
__global__ __launch_bounds__(K1_THREADS) void k1_region_median(
    const float* __restrict__ depth,
    const float* __restrict__ lm,
    const float* __restrict__ sf,
    const float* __restrict__ bbox)
{
    int wid  = threadIdx.x >> 5;
    int lane = threadIdx.x & 31;
    int idx  = blockIdx.x * (K1_THREADS / 32) + wid;
    if (idx >= NLM) return;
    int b = idx / LNUM;

    float sf0 = __ldg(sf + b * 2 + 0), sf1 = __ldg(sf + b * 2 + 1);
    float bx  = __ldg(bbox + b * 4 + 0), by = __ldg(bbox + b * 4 + 1);
    float lmx = __ldg(lm + (size_t)idx * 2 + 0);
    float lmy = __ldg(lm + (size_t)idx * 2 + 1);
    float fx = (lmx - bx) * sf0 / 224.0f * 2.0f - 1.0f;
    float fy = (lmy - by) * sf1 / 224.0f * 2.0f - 1.0f;

    const float* dimg = depth + (size_t)b * IMG * IMG;
    const float  INF  = __int_as_float(0x7f800000);

    float v0 = region_val(dimg, fx, fy, lane);
    float v1 = (lane < 17) ? region_val(dimg, fx, fy, lane + 32) : INF;

    // target rank mi = (clamp(count(v<=THR),1,48)+48)/2  — the reference's
    // sorted-region median with the transition-index rule.
    unsigned le0 = __ballot_sync(FULLM, v0 <= 1e-4f);
    unsigned le1 = __ballot_sync(FULLM, v1 <= 1e-4f) & MB;
    int k  = __popc(le0) + __popc(le1);
    int st = min(max(k, 1), R2 - 1);
    int mi = (st + R2 - 1) >> 1;

    // warp quickselect over the 49 values (warp-uniform control flow)
    unsigned a0 = FULLM, a1 = MB;
    float res;
    while (true) {
        bool  use0 = (a0 != 0u);
        int   pl   = use0 ? (__ffs(a0) - 1) : (__ffs(a1) - 1);
        float pa   = __shfl_sync(FULLM, v0, pl);
        float pb   = __shfl_sync(FULLM, v1, pl);
        float piv  = use0 ? pa : pb;
        unsigned l0  = __ballot_sync(FULLM, v0 <  piv);
        unsigned l1  = __ballot_sync(FULLM, v1 <  piv) & MB;
        unsigned q0  = __ballot_sync(FULLM, v0 <= piv);
        unsigned q1  = __ballot_sync(FULLM, v1 <= piv) & MB;
        int cl = __popc(l0) + __popc(l1);
        int ce = __popc(q0) + __popc(q1);
        if (mi >= cl && mi < ce) { res = piv; break; }
        if (mi < cl) { a0 &= l0;   a1 &= l1; }
        else         { a0 &= ~q0;  a1 &= ~q1; }
    }
    if (lane == 0) g_median[idx] = res;
}

// ---- K2: per-batch mom + mask + pairwise loss, SLICES blocks per batch ----
__global__ __launch_bounds__(K2_THREADS) void k2_pairwise(
    const float* __restrict__ rel,
    float* __restrict__ out)
{
    __shared__ float  smed[LNUM];
    __shared__ float  smask[LNUM];
    __shared__ float  s_mom;
    __shared__ double redL[K2_THREADS / 32], redM[K2_THREADS / 32];
    __shared__ bool   s_last;

    int blk   = blockIdx.x;
    int b     = blk / SLICES;
    int slice = blk - b * SLICES;
    int tid   = threadIdx.x;
    int wid   = tid >> 5;
    int lane  = tid & 31;

    float vraw = 0.0f;
    if (tid < LNUM) {
        vraw = g_median[b * LNUM + tid];
        smed[tid] = vraw;
    }
    __syncthreads();

    // lower median-of-medians (rank 33) via stable rank count (redundant per slice)
    if (tid < LNUM) {
        int r = 0;
#pragma unroll 4
        for (int j = 0; j < LNUM; j++) {
            float w = smed[j];
            r += (w < vraw || (w == vraw && j < tid)) ? 1 : 0;
        }
        if (r == (LNUM - 1) / 2) s_mom = vraw;
    }
    __syncthreads();
    if (tid < LNUM) {
        smask[tid] = (fabsf(vraw - s_mom) < (90.0f / 500.0f)) ? 1.0f : 0.0f;
        smed[tid]  = vraw * 500.0f;
    }
    __syncthreads();

    // pairwise diff / mask / smooth-L1. Output: out[0]=loss, outd=out+1,
    // outm=out+1+BS*LL. outd[base+e] has global index 1+base+e; base%4==0,
    // so e≡3 (mod 4) gives 16B-aligned float4 stores.
    float* outd = out + 1;
    float* outm = out + 1 + (size_t)BS * LL;
    const size_t base = (size_t)b * LL;
    const float* relb = rel + base;
    float accL = 0.0f, accM = 0.0f;

    if (slice == 0 && tid < 4) {        // head e=0,1,2 and tail e=4623
        int e = (tid < 3) ? tid : (LL - 1);
        int i = e / LNUM;
        int j = e - i * LNUM;
        float diff = smed[i] - smed[j];
        float mk   = smask[i] * smask[j];
        float d    = relb[e] - diff;
        float ad   = fabsf(d);
        float c    = fminf(ad, 1.0f);
        float le   = c * (ad - 0.5f * c);
        outd[base + e] = diff;
        outm[base + e] = mk;
        accL += le * mk;
        accM += mk;
    }

    int gstart = slice * GRP_PER_SLICE;
    int gend   = min(gstart + GRP_PER_SLICE, NGRP);
    for (int g = gstart + tid; g < gend; g += K2_THREADS) {
        int e0 = 3 + (g << 2);
        int i0 = e0 / LNUM;
        int j0 = e0 - i0 * LNUM;
        float dvv[4], mvv[4];
#pragma unroll
        for (int n = 0; n < 4; n++) {
            int jn = j0 + n;
            int wrap = (jn >= LNUM) ? 1 : 0;
            int in = i0 + wrap;
            jn -= LNUM * wrap;
            float diff = smed[in] - smed[jn];
            float mk   = smask[in] * smask[jn];
            float d    = relb[e0 + n] - diff;
            float ad   = fabsf(d);
            float c    = fminf(ad, 1.0f);
            float le   = c * (ad - 0.5f * c);
            dvv[n] = diff;
            mvv[n] = mk;
            accL += le * mk;
            accM += mk;
        }
        *reinterpret_cast<float4*>(outd + base + e0) =
            make_float4(dvv[0], dvv[1], dvv[2], dvv[3]);
        *reinterpret_cast<float4*>(outm + base + e0) =
            make_float4(mvv[0], mvv[1], mvv[2], mvv[3]);
    }

    // block reduce (double) + global atomics + last-block finalize
    double dL = (double)accL, dM = (double)accM;
#pragma unroll
    for (int o = 16; o > 0; o >>= 1) {
        dL += __shfl_down_sync(FULLM, dL, o);
        dM += __shfl_down_sync(FULLM, dM, o);
    }
    if (lane == 0) { redL[wid] = dL; redM[wid] = dM; }
    __syncthreads();
    if (tid == 0) {
        double tL = 0.0, tM = 0.0;
#pragma unroll
        for (int w = 0; w < K2_THREADS / 32; w++) { tL += redL[w]; tM += redM[w]; }
        atomicAdd(&g_sumL, tL);
        atomicAdd(&g_sumM, tM);
        __threadfence();
        unsigned n = atomicAdd(&g_done, 1u);
        s_last = (n == (unsigned)(BS * SLICES) - 1u);
    }
    __syncthreads();

    if (s_last && tid == 0) {
        __threadfence();
        double L = g_sumL, M = g_sumM;
        out[0] = (float)(L / (M + 1e-4));
        g_sumL = 0.0; g_sumM = 0.0; g_done = 0u;
    }
}

extern "C" void kernel_launch(void* const* d_in, const int* in_sizes, int n_in,
                              void* d_out, int out_size)
{
    const float* rel   = (const float*)d_in[0];   // [BS, L, L]
    const float* depth = (const float*)d_in[1];   // [BS, 1, IMG, IMG]
    const float* lm    = (const float*)d_in[2];   // [BS, L, 2]
    const float* sf    = (const float*)d_in[3];   // [BS, 2]
    const float* bbox  = (const float*)d_in[4];   // [BS, 4]
    float* out = (float*)d_out;                   // [loss | diff | mask]

    const int k1_blocks = (NLM + (K1_THREADS / 32) - 1) / (K1_THREADS / 32);
    k1_region_median<<<k1_blocks, K1_THREADS>>>(depth, lm, sf, bbox);
    k2_pairwise<<<BS * SLICES, K2_THREADS>>>(rel, out);
}

// round 6
// speedup vs baseline: 1.2856x; 1.2245x over previous
#include <cuda_runtime.h>
#include <math.h>
#include <stdint.h>

#define BS    512
#define LNUM  68
#define IMG   224
#define RS    7
#define R2    49
#define LL    (LNUM * LNUM)     // 4624
#define NTHR  544               // 17 warps, 4 landmarks per warp
#define FULLM 0xFFFFFFFFu
#define MB    0x1FFFFu          // lanes 0..16 hold slots 32..48
#define NGRP  ((LL - 4) / 4)    // 1155 float4 store groups per batch

__device__ double   g_sumL = 0.0;
__device__ double   g_sumM = 0.0;
__device__ unsigned g_done = 0u;

__device__ __forceinline__ uint32_t smem_u32(const void* p) {
    return (uint32_t)__cvta_generic_to_shared(p);
}

// Sample one region slot s (0..48); exact replica of the reference's
// grid_sample-nearest arithmetic (rintf == jnp.round, half-even).
__device__ __forceinline__ float region_val(const float* __restrict__ dimg,
                                            float fx, float fy, int s)
{
    int p = s / RS, q = s - p * RS;
    float xp = (p == RS - 1) ? 3.5f : (-3.5f + (float)p * (7.0f / 6.0f));
    float xq = (q == RS - 1) ? 3.5f : (-3.5f + (float)q * (7.0f / 6.0f));
    xp = xp / 224.0f * 2.0f;
    xq = xq / 224.0f * 2.0f;
    float gy = fy + xp;                       // offsets[p][q] = (x[q], x[p])
    float gx = fx + xq;
    float iy = ((gy + 1.0f) * 224.0f - 1.0f) * 0.5f;
    float ix = ((gx + 1.0f) * 224.0f - 1.0f) * 0.5f;
    int yi = (int)rintf(iy);
    int xi = (int)rintf(ix);
    bool v = (yi >= 0) & (yi < IMG) & (xi >= 0) & (xi < IMG);
    int yc = min(max(yi, 0), IMG - 1);
    int xc = min(max(xi, 0), IMG - 1);
    float val = __ldg(dimg + yc * IMG + xc);
    return v ? val : 0.0f;
}

// Warp quickselect for rank mi over the 49 region values (2 slots/lane).
__device__ __forceinline__ float warp_region_median(float v0, float v1)
{
    unsigned le0 = __ballot_sync(FULLM, v0 <= 1e-4f);
    unsigned le1 = __ballot_sync(FULLM, v1 <= 1e-4f) & MB;
    int k  = __popc(le0) + __popc(le1);
    int st = min(max(k, 1), R2 - 1);
    int mi = (st + R2 - 1) >> 1;             // (clamp(cnt,1,48)+48)/2

    unsigned a0 = FULLM, a1 = MB;
    while (true) {
        bool  use0 = (a0 != 0u);
        int   pl   = use0 ? (__ffs(a0) - 1) : (__ffs(a1) - 1);
        float pa   = __shfl_sync(FULLM, v0, pl);
        float pb   = __shfl_sync(FULLM, v1, pl);
        float piv  = use0 ? pa : pb;
        unsigned l0 = __ballot_sync(FULLM, v0 <  piv);
        unsigned l1 = __ballot_sync(FULLM, v1 <  piv) & MB;
        unsigned q0 = __ballot_sync(FULLM, v0 <= piv);
        unsigned q1 = __ballot_sync(FULLM, v1 <= piv) & MB;
        int cl = __popc(l0) + __popc(l1);
        int ce = __popc(q0) + __popc(q1);
        if (mi >= cl && mi < ce) return piv;
        if (mi < cl) { a0 &= l0;   a1 &= l1; }
        else         { a0 &= ~q0;  a1 &= ~q1; }
    }
}

__global__ __launch_bounds__(NTHR, 3) void fused_kernel(
    const float* __restrict__ rel,
    const float* __restrict__ depth,
    const float* __restrict__ lm,
    const float* __restrict__ sf,
    const float* __restrict__ bbox,
    float* __restrict__ out)
{
    __shared__ float  s_rel[LL];             // 18496 B, staged via cp.async.bulk
    __shared__ float  smed[LNUM];
    __shared__ float  smask[LNUM];
    __shared__ float  s_mom;
    __shared__ double redL[17], redM[17];
    __shared__ bool   s_last;
    __shared__ __align__(8) unsigned long long s_mbar;

    int b    = blockIdx.x;
    int tid  = threadIdx.x;
    int wid  = tid >> 5;
    int lane = tid & 31;

    const size_t base = (size_t)b * LL;
    const float* relb = rel + base;

    // ---- phase 0: kick off bulk copy rel[batch] -> smem (overlaps phase 1/2) ----
    uint32_t mb = smem_u32(&s_mbar);
    if (tid == 0) {
        asm volatile("mbarrier.init.shared.b64 [%0], 1;" :: "r"(mb) : "memory");
        asm volatile("fence.proxy.async.shared::cta;" ::: "memory");
        asm volatile("mbarrier.arrive.expect_tx.shared.b64 _, [%0], %1;"
                     :: "r"(mb), "r"((uint32_t)(LL * 4)) : "memory");
        asm volatile("cp.async.bulk.shared::cta.global.mbarrier::complete_tx::bytes "
                     "[%0], [%1], %2, [%3];"
                     :: "r"(smem_u32(s_rel)), "l"(relb),
                        "r"((uint32_t)(LL * 4)), "r"(mb) : "memory");
    }

    // ---- phase 1: region medians, 4 landmarks per warp ----
    float sf0 = sf[b * 2 + 0], sf1 = sf[b * 2 + 1];
    float bx  = bbox[b * 4 + 0], by = bbox[b * 4 + 1];
    const float* dimg = depth + (size_t)b * IMG * IMG;
    const float  INF  = __int_as_float(0x7f800000);

    float v0[4], v1[4];
#pragma unroll
    for (int li = 0; li < 4; li++) {
        int l = wid * 4 + li;
        float lmx = lm[((size_t)b * LNUM + l) * 2 + 0];
        float lmy = lm[((size_t)b * LNUM + l) * 2 + 1];
        float fx = (lmx - bx) * sf0 / 224.0f * 2.0f - 1.0f;
        float fy = (lmy - by) * sf1 / 224.0f * 2.0f - 1.0f;
        v0[li] = region_val(dimg, fx, fy, lane);
        v1[li] = (lane < 17) ? region_val(dimg, fx, fy, lane + 32) : INF;
    }
#pragma unroll
    for (int li = 0; li < 4; li++) {
        float med = warp_region_median(v0[li], v1[li]);
        if (lane == 0) smed[wid * 4 + li] = med;
    }
    __syncthreads();

    // ---- phase 2: lower median-of-medians (rank 33) + mask ----
    float vraw = 0.0f;
    if (tid < LNUM) {
        vraw = smed[tid];
        int r = 0;
#pragma unroll 4
        for (int j = 0; j < LNUM; j++) {
            float w = smed[j];
            r += (w < vraw || (w == vraw && j < tid)) ? 1 : 0;  // stable rank
        }
        if (r == (LNUM - 1) / 2) s_mom = vraw;
    }
    __syncthreads();
    if (tid < LNUM) {
        smask[tid] = (fabsf(vraw - s_mom) < (90.0f / 500.0f)) ? 1.0f : 0.0f;
        smed[tid]  = vraw * 500.0f;
    }
    __syncthreads();

    // ---- wait for staged rel (normally complete by now: TRYWAIT fast path) ----
    {
        uint32_t done;
        asm volatile(
            "{\n\t.reg .pred p;\n\t"
            "mbarrier.try_wait.parity.acquire.cta.shared::cta.b64 p, [%1], %2;\n\t"
            "selp.b32 %0, 1, 0, p;\n\t}"
            : "=r"(done) : "r"(mb), "r"(0u) : "memory");
        while (!done) {
            asm volatile(
                "{\n\t.reg .pred p;\n\t"
                "mbarrier.try_wait.parity.acquire.cta.shared::cta.b64 p, [%1], %2;\n\t"
                "selp.b32 %0, 1, 0, p;\n\t}"
                : "=r"(done) : "r"(mb), "r"(0u) : "memory");
        }
    }

    // ---- phase 3: pairwise diff / mask / smooth-L1, float4 stores ----
    // out[0]=loss, outd=out+1, outm=out+1+BS*LL. outd[base+e] has global float
    // index 1+base+e; base%4==0 so e≡3 (mod 4) gives 16B-aligned float4 stores.
    float* outd = out + 1;
    float* outm = out + 1 + (size_t)BS * LL;
    float accL = 0.0f, accM = 0.0f;

    if (tid < 4) {                      // head e=0,1,2 and tail e=4623
        int e = (tid < 3) ? tid : (LL - 1);
        int i = e / LNUM;
        int j = e - i * LNUM;
        float diff = smed[i] - smed[j];
        float mk   = smask[i] * smask[j];
        float d    = s_rel[e] - diff;
        float ad   = fabsf(d);
        float c    = fminf(ad, 1.0f);
        float le   = c * (ad - 0.5f * c);
        outd[base + e] = diff;
        outm[base + e] = mk;
        accL += le * mk;
        accM += mk;
    }

    for (int g = tid; g < NGRP; g += NTHR) {
        int e0 = 3 + (g << 2);
        int i0 = e0 / LNUM;
        int j0 = e0 - i0 * LNUM;
        float dvv[4], mvv[4];
#pragma unroll
        for (int n = 0; n < 4; n++) {
            int jn = j0 + n;
            int wrap = (jn >= LNUM) ? 1 : 0;
            int in = i0 + wrap;
            jn -= LNUM * wrap;
            float diff = smed[in] - smed[jn];
            float mk   = smask[in] * smask[jn];
            float d    = s_rel[e0 + n] - diff;
            float ad   = fabsf(d);
            float c    = fminf(ad, 1.0f);
            float le   = c * (ad - 0.5f * c);
            dvv[n] = diff;
            mvv[n] = mk;
            accL += le * mk;
            accM += mk;
        }
        *reinterpret_cast<float4*>(outd + base + e0) =
            make_float4(dvv[0], dvv[1], dvv[2], dvv[3]);
        *reinterpret_cast<float4*>(outm + base + e0) =
            make_float4(mvv[0], mvv[1], mvv[2], mvv[3]);
    }

    // ---- block reduce (double) + global atomics + last-block finalize ----
    double dL = (double)accL, dM = (double)accM;
#pragma unroll
    for (int o = 16; o > 0; o >>= 1) {
        dL += __shfl_down_sync(FULLM, dL, o);
        dM += __shfl_down_sync(FULLM, dM, o);
    }
    if (lane == 0) { redL[wid] = dL; redM[wid] = dM; }
    __syncthreads();
    if (tid == 0) {
        double tL = 0.0, tM = 0.0;
#pragma unroll
        for (int w = 0; w < 17; w++) { tL += redL[w]; tM += redM[w]; }
        atomicAdd(&g_sumL, tL);
        atomicAdd(&g_sumM, tM);
        __threadfence();
        unsigned n = atomicAdd(&g_done, 1u);
        s_last = (n == BS - 1);
    }
    __syncthreads();

    if (s_last && tid == 0) {
        __threadfence();
        double L = g_sumL, M = g_sumM;
        out[0] = (float)(L / (M + 1e-4));
        g_sumL = 0.0; g_sumM = 0.0; g_done = 0u;
    }
}

extern "C" void kernel_launch(void* const* d_in, const int* in_sizes, int n_in,
                              void* d_out, int out_size)
{
    const float* rel   = (const float*)d_in[0];   // [BS, L, L]
    const float* depth = (const float*)d_in[1];   // [BS, 1, IMG, IMG]
    const float* lm    = (const float*)d_in[2];   // [BS, L, 2]
    const float* sf    = (const float*)d_in[3];   // [BS, 2]
    const float* bbox  = (const float*)d_in[4];   // [BS, 4]
    float* out = (float*)d_out;                   // [loss | diff | mask]

    fused_kernel<<<BS, NTHR>>>(rel, depth, lm, sf, bbox, out);
}

// round 7
// speedup vs baseline: 1.3805x; 1.0738x over previous
#include <cuda_runtime.h>
#include <math.h>
#include <stdint.h>

#define BS    512
#define LNUM  68
#define IMG   224
#define RS    7
#define R2    49
#define LL    (LNUM * LNUM)     // 4624
#define NTHR  512               // 16 warps
#define NWARP 16
#define FULLM 0xFFFFFFFFu
#define MB    0x1FFFFu          // lanes 0..16 hold slots 32..48
#define NGRP  ((LL - 4) / 4)    // 1155 float4 store groups per batch

__device__ double   g_sumL = 0.0;
__device__ double   g_sumM = 0.0;
__device__ unsigned g_done = 0u;

__device__ __forceinline__ uint32_t smem_u32(const void* p) {
    return (uint32_t)__cvta_generic_to_shared(p);
}

// linspace(-3.5,3.5,7)[k] / 224 * 2 — identical op order to the reference.
__device__ __forceinline__ float xval(int k) {
    float x = -3.5f + (float)k * (7.0f / 6.0f);
    if (k == RS - 1) x = 3.5f;
    return x / 224.0f * 2.0f;
}

// One region sample given hoisted per-slot offsets (cx, cy); exact replica of
// the reference's grid_sample-nearest arithmetic (rintf == jnp.round).
__device__ __forceinline__ float sample(const float* __restrict__ dimg,
                                        float fx, float fy, float cx, float cy)
{
    float gy = fy + cy;
    float gx = fx + cx;
    float iy = ((gy + 1.0f) * 224.0f - 1.0f) * 0.5f;
    float ix = ((gx + 1.0f) * 224.0f - 1.0f) * 0.5f;
    int yi = (int)rintf(iy);
    int xi = (int)rintf(ix);
    bool v = (yi >= 0) & (yi < IMG) & (xi >= 0) & (xi < IMG);
    int yc = min(max(yi, 0), IMG - 1);
    int xc = min(max(xi, 0), IMG - 1);
    float val = __ldg(dimg + yc * IMG + xc);
    return v ? val : 0.0f;
}

// Warp quickselect for the region median (rank mi per the transition rule).
__device__ __forceinline__ float warp_region_median(float v0, float v1)
{
    unsigned le0 = __ballot_sync(FULLM, v0 <= 1e-4f);
    unsigned le1 = __ballot_sync(FULLM, v1 <= 1e-4f) & MB;
    int k  = __popc(le0) + __popc(le1);
    int st = min(max(k, 1), R2 - 1);
    int mi = (st + R2 - 1) >> 1;             // (clamp(cnt,1,48)+48)/2

    unsigned a0 = FULLM, a1 = MB;
    while (true) {
        bool     use0 = (a0 != 0u);
        unsigned am   = use0 ? a0 : a1;
        int      pl   = __ffs(am) - 1;
        float    cand = use0 ? v0 : v1;      // SEL, then single SHFL
        float    piv  = __shfl_sync(FULLM, cand, pl);
        unsigned l0 = __ballot_sync(FULLM, v0 <  piv);
        unsigned l1 = __ballot_sync(FULLM, v1 <  piv) & MB;
        unsigned q0 = __ballot_sync(FULLM, v0 <= piv);
        unsigned q1 = __ballot_sync(FULLM, v1 <= piv) & MB;
        int cl = __popc(l0) + __popc(l1);
        int ce = __popc(q0) + __popc(q1);
        if (mi >= cl && mi < ce) return piv;
        if (mi < cl) { a0 &= l0;   a1 &= l1; }
        else         { a0 &= ~q0;  a1 &= ~q1; }
    }
}

__global__ __launch_bounds__(NTHR, 4) void fused_kernel(
    const float* __restrict__ rel,
    const float* __restrict__ depth,
    const float* __restrict__ lm,
    const float* __restrict__ sf,
    const float* __restrict__ bbox,
    float* __restrict__ out)
{
    __shared__ float  s_rel[LL];             // staged via cp.async.bulk
    __shared__ float  smed[LNUM];
    __shared__ float  smask[LNUM];
    __shared__ float  s_mom;
    __shared__ int    s_cnt[3];
    __shared__ double redL[NWARP];
    __shared__ bool   s_last;
    __shared__ __align__(8) unsigned long long s_mbar;

    int b    = blockIdx.x;
    int tid  = threadIdx.x;
    int wid  = tid >> 5;
    int lane = tid & 31;

    const size_t base = (size_t)b * LL;
    const float* relb = rel + base;

    // ---- phase 0: bulk copy rel[batch] -> smem (overlaps phase 1/2) ----
    uint32_t mb = smem_u32(&s_mbar);
    if (tid == 0) {
        asm volatile("mbarrier.init.shared.b64 [%0], 1;" :: "r"(mb) : "memory");
        asm volatile("fence.proxy.async.shared::cta;" ::: "memory");
        asm volatile("mbarrier.arrive.expect_tx.shared.b64 _, [%0], %1;"
                     :: "r"(mb), "r"((uint32_t)(LL * 4)) : "memory");
        asm volatile("cp.async.bulk.shared::cta.global.mbarrier::complete_tx::bytes "
                     "[%0], [%1], %2, [%3];"
                     :: "r"(smem_u32(s_rel)), "l"(relb),
                        "r"((uint32_t)(LL * 4)), "r"(mb) : "memory");
    }

    // ---- hoisted per-lane slot constants (independent of landmark) ----
    int p0 = lane / RS,        q0 = lane - RS * p0;
    int s1 = lane + 32;
    int p1 = s1 / RS,          q1 = s1 - RS * p1;
    float cy0 = xval(p0), cx0 = xval(q0);
    float cy1 = xval(p1), cx1 = xval(q1);
    bool  hi_ok = (lane < 17);

    float sf0 = sf[b * 2 + 0], sf1 = sf[b * 2 + 1];
    float bx  = bbox[b * 4 + 0], by = bbox[b * 4 + 1];
    const float* dimg = depth + (size_t)b * IMG * IMG;
    const float  INF  = __int_as_float(0x7f800000);

    // ---- phase 1: region medians; warp w -> landmarks 4w..4w+3 (+64+w if w<4)
    int nl = (wid < 4) ? 5 : 4;
#define LM_IDX(i) (((i) < 4) ? (wid * 4 + (i)) : (64 + wid))

    float v0, v1;
    {   // prefetch landmark 0
        int l = LM_IDX(0);
        float2 lxy = *reinterpret_cast<const float2*>(lm + ((size_t)b * LNUM + l) * 2);
        float fx = (lxy.x - bx) * sf0 / 224.0f * 2.0f - 1.0f;
        float fy = (lxy.y - by) * sf1 / 224.0f * 2.0f - 1.0f;
        v0 = sample(dimg, fx, fy, cx0, cy0);
        v1 = hi_ok ? sample(dimg, fx, fy, cx1, cy1) : INF;
    }
    for (int i = 0; i < nl; i++) {
        float nv0 = 0.0f, nv1 = INF;
        if (i + 1 < nl) {                    // prefetch next while selecting
            int l = LM_IDX(i + 1);
            float2 lxy = *reinterpret_cast<const float2*>(lm + ((size_t)b * LNUM + l) * 2);
            float fx = (lxy.x - bx) * sf0 / 224.0f * 2.0f - 1.0f;
            float fy = (lxy.y - by) * sf1 / 224.0f * 2.0f - 1.0f;
            nv0 = sample(dimg, fx, fy, cx0, cy0);
            nv1 = hi_ok ? sample(dimg, fx, fy, cx1, cy1) : INF;
        }
        float med = warp_region_median(v0, v1);
        if (lane == 0) smed[LM_IDX(i)] = med;
        v0 = nv0; v1 = nv1;
    }
#undef LM_IDX
    __syncthreads();

    // ---- phase 2: lower median-of-medians (rank 33) + mask + count ----
    float vraw = 0.0f;
    if (tid < LNUM) {
        vraw = smed[tid];
        int r = 0;
#pragma unroll 4
        for (int j = 0; j < LNUM; j++) {
            float w = smed[j];
            r += (w < vraw || (w == vraw && j < tid)) ? 1 : 0;  // stable rank
        }
        if (r == (LNUM - 1) / 2) s_mom = vraw;
    }
    __syncthreads();
    bool mbit = false;
    if (tid < LNUM) {
        mbit = fabsf(vraw - s_mom) < (90.0f / 500.0f);
        smask[tid] = mbit ? 1.0f : 0.0f;
        smed[tid]  = vraw * 500.0f;
    }
    unsigned bal = __ballot_sync(FULLM, mbit);
    if (lane == 0 && wid < 3) s_cnt[wid] = __popc(bal);
    __syncthreads();

    // ---- wait for staged rel (TRYWAIT fast path, normally complete) ----
    {
        uint32_t done;
        do {
            asm volatile(
                "{\n\t.reg .pred p;\n\t"
                "mbarrier.try_wait.parity.acquire.cta.shared::cta.b64 p, [%1], %2;\n\t"
                "selp.b32 %0, 1, 0, p;\n\t}"
                : "=r"(done) : "r"(mb), "r"(0u) : "memory");
        } while (!done);
    }

    // ---- phase 3: pairwise diff / mask / smooth-L1, float4 stores ----
    // out[0]=loss, outd=out+1, outm=out+1+BS*LL. outd[base+e] has global float
    // index 1+base+e; base%4==0 so e≡3 (mod 4) gives 16B-aligned float4 stores.
    float* outd = out + 1;
    float* outm = out + 1 + (size_t)BS * LL;
    float accL = 0.0f;

    if (tid < 4) {                      // head e=0,1,2 and tail e=4623
        int e = (tid < 3) ? tid : (LL - 1);
        int i = e / LNUM;
        int j = e - i * LNUM;
        float diff = smed[i] - smed[j];
        float mk   = smask[i] * smask[j];
        float d    = s_rel[e] - diff;
        float ad   = fabsf(d);
        float c    = fminf(ad, 1.0f);
        float le   = c * (ad - 0.5f * c);
        outd[base + e] = diff;
        outm[base + e] = mk;
        accL += le * mk;
    }

    for (int g = tid; g < NGRP; g += NTHR) {
        int e0 = 3 + (g << 2);
        int i0 = e0 / LNUM;
        int j0 = e0 - i0 * LNUM;
        float dvv[4], mvv[4];
#pragma unroll
        for (int n = 0; n < 4; n++) {
            int jn = j0 + n;
            int wrap = (jn >= LNUM) ? 1 : 0;
            int in = i0 + wrap;
            jn -= LNUM * wrap;
            float diff = smed[in] - smed[jn];
            float mk   = smask[in] * smask[jn];
            float d    = s_rel[e0 + n] - diff;
            float ad   = fabsf(d);
            float c    = fminf(ad, 1.0f);
            float le   = c * (ad - 0.5f * c);
            dvv[n] = diff;
            mvv[n] = mk;
            accL += le * mk;
        }
        *reinterpret_cast<float4*>(outd + base + e0) =
            make_float4(dvv[0], dvv[1], dvv[2], dvv[3]);
        *reinterpret_cast<float4*>(outm + base + e0) =
            make_float4(mvv[0], mvv[1], mvv[2], mvv[3]);
    }

    // ---- block reduce + global atomics + last-block finalize ----
    double dL = (double)accL;
#pragma unroll
    for (int o = 16; o > 0; o >>= 1)
        dL += __shfl_down_sync(FULLM, dL, o);
    if (lane == 0) redL[wid] = dL;
    __syncthreads();
    if (tid == 0) {
        double tL = 0.0;
#pragma unroll
        for (int w = 0; w < NWARP; w++) tL += redL[w];
        double cnt = (double)(s_cnt[0] + s_cnt[1] + s_cnt[2]);
        atomicAdd(&g_sumL, tL);
        atomicAdd(&g_sumM, cnt * cnt);      // sum_ij mi*mj == (sum m)^2
        __threadfence();
        unsigned n = atomicAdd(&g_done, 1u);
        s_last = (n == BS - 1);
    }
    __syncthreads();

    if (s_last && tid == 0) {
        __threadfence();
        double L = g_sumL, M = g_sumM;
        out[0] = (float)(L / (M + 1e-4));
        g_sumL = 0.0; g_sumM = 0.0; g_done = 0u;
    }
}

extern "C" void kernel_launch(void* const* d_in, const int* in_sizes, int n_in,
                              void* d_out, int out_size)
{
    const float* rel   = (const float*)d_in[0];   // [BS, L, L]
    const float* depth = (const float*)d_in[1];   // [BS, 1, IMG, IMG]
    const float* lm    = (const float*)d_in[2];   // [BS, L, 2]
    const float* sf    = (const float*)d_in[3];   // [BS, 2]
    const float* bbox  = (const float*)d_in[4];   // [BS, 4]
    float* out = (float*)d_out;                   // [loss | diff | mask]

    fused_kernel<<<BS, NTHR>>>(rel, depth, lm, sf, bbox, out);
}